// round 7
// baseline (speedup 1.0000x reference)
#include <cuda_runtime.h>

// Problem constants (fixed by the reference)
constexpr int N  = 100000;
constexpr int E  = 1600000;
constexpr int IN = 32;
constexpr int H  = 64;
constexpr int L  = 16;
constexpr int G  = 64;

constexpr int SCAN_CHUNK = 512;
constexpr int NB_SCAN = (N + SCAN_CHUNK - 1) / SCAN_CHUNK;  // 196

#define CDIV(a, b) (((a) + (b) - 1) / (b))

typedef unsigned long long ull;

// ---------------- packed f32x2 helpers ----------------
__device__ __forceinline__ ull pack2(float x, float y) {
    ull r;
    asm("mov.b64 %0, {%1, %2};" : "=l"(r) : "f"(x), "f"(y));
    return r;
}
__device__ __forceinline__ void unpack2(float& x, float& y, ull v) {
    asm("mov.b64 {%0, %1}, %2;" : "=f"(x), "=f"(y) : "l"(v));
}
__device__ __forceinline__ void fma2(ull& d, ull a, ull b) {
    asm("fma.rn.f32x2 %0, %1, %2, %0;" : "+l"(d) : "l"(a), "l"(b));
}

// ---------------- device scratch (no allocations allowed) ----------------
__device__ float g_buf0[N * H];
__device__ float g_buf1[N * H];
__device__ float g_dinv[N];
__device__ int   g_deg[N];
__device__ int   g_rowptr[N + 1];
__device__ int   g_cursor[N];
__device__ int   g_srcs[E];
__device__ int   g_bsum[256];
__device__ float g_pool[G * H];
__device__ float g_cnt[G];
__device__ float g_z[G * L];

// ---------------- degree histogram ----------------
__global__ void k_hist(const int* __restrict__ dst) {
    int e = blockIdx.x * blockDim.x + threadIdx.x;
    if (e < E) atomicAdd(&g_deg[dst[e]], 1);
}

// ---------------- scan pass 1 (also computes dinv) ----------------
__global__ void k_scan1() {
    __shared__ int s[SCAN_CHUNK];
    int t = threadIdx.x;
    int i = blockIdx.x * SCAN_CHUNK + t;
    int v = (i < N) ? g_deg[i] : 0;
    if (i < N) g_dinv[i] = rsqrtf((float)v + 1.0f);
    s[t] = v;
    __syncthreads();
#pragma unroll
    for (int off = 1; off < SCAN_CHUNK; off <<= 1) {
        int x = (t >= off) ? s[t - off] : 0;
        __syncthreads();
        s[t] += x;
        __syncthreads();
    }
    if (i < N) g_rowptr[i] = s[t] - v;
    if (t == SCAN_CHUNK - 1) g_bsum[blockIdx.x] = s[t];
}

// ---------------- fused scan2+scan3 ----------------
__global__ void k_scan23() {
    __shared__ int s[256];
    __shared__ int excl[256];
    int t = threadIdx.x;
    int v = (t < NB_SCAN) ? g_bsum[t] : 0;
    s[t] = v;
    __syncthreads();
#pragma unroll
    for (int off = 1; off < 256; off <<= 1) {
        int x = (t >= off) ? s[t - off] : 0;
        __syncthreads();
        s[t] += x;
        __syncthreads();
    }
    excl[t] = s[t] - v;
    __syncthreads();
    int i = blockIdx.x * blockDim.x + t;
    if (i < N) {
        int r = g_rowptr[i] + excl[i / SCAN_CHUNK];
        g_rowptr[i] = r;
        g_cursor[i] = r;
    }
    if (i == 0) g_rowptr[N] = E;
}

__global__ void k_fill(const int* __restrict__ src, const int* __restrict__ dst) {
    int e = blockIdx.x * blockDim.x + threadIdx.x;
    if (e >= E) return;
    int pos = atomicAdd(&g_cursor[dst[e]], 1);
    g_srcs[pos] = src[e];
}

// ---------------- prescale: P0 = x * dinv[row]  (C=32) ----------------
__global__ void k_prescale32(const float* __restrict__ X, float* __restrict__ Y) {
    int idx = blockIdx.x * blockDim.x + threadIdx.x;
    if (idx >= N * 8) return;
    int i = idx >> 3;
    float d = g_dinv[i];
    float4 v = ((const float4*)X)[idx];
    float4 o = {v.x * d, v.y * d, v.z * d, v.w * d};
    ((float4*)Y)[idx] = o;
}

// =====================================================================
// Fused gather + matvec, warp-local (no block barrier).
//   Per node (handled by Q=CIN/4 lanes):
//     A = dinv * (sum_nbr P[nbr] + P[self])  -> smem staging row
//     __syncwarp
//     out = A @ W  (f32x2), per-lane CPT cols
//   MODE 0: Y = dinv * relu(out + b)   (next layer's P)
//   MODE 1: pool relu(out + b) via run-length atomics; no Y write
//   MODE 2: Y = relu(out + b)          (unscaled h, for mm-first dec1)
// =====================================================================
template <int CIN, int COUT, int MODE>
__global__ void __launch_bounds__(256)
k_gmm(const float* __restrict__ X, const float* __restrict__ W,
      const float* __restrict__ bias, float* __restrict__ Y,
      const int* __restrict__ batch) {
    constexpr int Q = CIN / 4;          // lanes per node
    constexpr int GROUPS = 256 / Q;
    constexpr int ROUNDS = 8;
    constexpr int NPB = GROUPS * ROUNDS;
    constexpr int CPT = COUT / Q;       // cols per lane (4 or 8)
    constexpr int PITCH = CIN + 1;
    __shared__ float sW[CIN * COUT];
    __shared__ float sA[GROUPS * PITCH];

    int t = threadIdx.x;
    for (int i = t; i < CIN * COUT / 4; i += 256)
        ((float4*)sW)[i] = ((const float4*)W)[i];
    __syncthreads();

    int q = t % Q, g = t / Q;
    int c0 = q * CPT;
    float bv[CPT];
#pragma unroll
    for (int j = 0; j < CPT; j++) bv[j] = bias[c0 + j];

    int row0 = blockIdx.x * NPB + g * ROUNDS;   // this group's 8 consecutive nodes
    const float4* Xv = (const float4*)X;
    const ull zz = pack2(0.f, 0.f);

    // MODE 1 run-length state
    float pacc[CPT];
    float cntacc = 0.f;
    int cur = -1;
    if (MODE == 1) {
#pragma unroll
        for (int j = 0; j < CPT; j++) pacc[j] = 0.f;
    }

    for (int r = 0; r < ROUNDS; r++) {
        int node = row0 + r;
        bool valid = node < N;
        float d = 1.0f;
        if (valid) {
            float4 acc = Xv[(size_t)node * Q + q];
            int beg = g_rowptr[node], end = g_rowptr[node + 1];
#pragma unroll 4
            for (int j = beg; j < end; j++) {
                float4 v = Xv[(size_t)g_srcs[j] * Q + q];
                acc.x += v.x; acc.y += v.y; acc.z += v.z; acc.w += v.w;
            }
            d = g_dinv[node];
            float* p = sA + g * PITCH + q * 4;
            p[0] = acc.x * d; p[1] = acc.y * d; p[2] = acc.z * d; p[3] = acc.w * d;
        }
        __syncwarp();
        if (valid) {
            ull acc2[CPT / 2];
#pragma unroll
            for (int j = 0; j < CPT / 2; j++) acc2[j] = zz;
#pragma unroll
            for (int k = 0; k < CIN; k++) {
                float a = sA[g * PITCH + k];
                ull a2 = pack2(a, a);
#pragma unroll
                for (int v = 0; v < CPT / 4; v++) {
                    ulonglong2 bb = *(const ulonglong2*)(sW + k * COUT + c0 + v * 4);
                    fma2(acc2[v * 2 + 0], a2, bb.x);
                    fma2(acc2[v * 2 + 1], a2, bb.y);
                }
            }
            float o[CPT];
#pragma unroll
            for (int j = 0; j < CPT / 2; j++) unpack2(o[2 * j], o[2 * j + 1], acc2[j]);

            if (MODE == 1) {
                int gid = batch[node];
                if (gid != cur) {
                    if (cur >= 0) {
#pragma unroll
                        for (int j = 0; j < CPT; j++)
                            atomicAdd(&g_pool[cur * H + c0 + j], pacc[j]);
                        if (q == 0) atomicAdd(&g_cnt[cur], cntacc);
                    }
                    cur = gid; cntacc = 0.f;
#pragma unroll
                    for (int j = 0; j < CPT; j++) pacc[j] = 0.f;
                }
#pragma unroll
                for (int j = 0; j < CPT; j++)
                    pacc[j] += fmaxf(o[j] + bv[j], 0.f);
                cntacc += 1.f;
            } else {
#pragma unroll
                for (int j = 0; j < CPT; j++) {
                    float v = fmaxf(o[j] + bv[j], 0.f);
                    o[j] = (MODE == 0) ? v * d : v;
                }
#pragma unroll
                for (int v = 0; v < CPT / 4; v++)
                    *(float4*)(Y + (size_t)node * COUT + c0 + v * 4) =
                        make_float4(o[v*4+0], o[v*4+1], o[v*4+2], o[v*4+3]);
            }
        }
        __syncwarp();   // protect sA before next round's overwrite
    }
    if (MODE == 1 && cur >= 0) {
#pragma unroll
        for (int j = 0; j < CPT; j++)
            atomicAdd(&g_pool[cur * H + c0 + j], pacc[j]);
        if (q == 0) atomicAdd(&g_cnt[cur], cntacc);
    }
}

// ---------------- CSR gather (standalone, for final dec1 at C=32) ----------------
template <int C, bool BIAS, bool RELU>
__global__ void k_gather(const float* __restrict__ X, const float* __restrict__ bias,
                         float* __restrict__ Y) {
    constexpr int Q = C / 4;
    constexpr int NPB = 256 / Q;
    int t = threadIdx.x;
    int node = blockIdx.x * NPB + t / Q;
    int q = t % Q;
    if (node >= N) return;
    int beg = g_rowptr[node];
    int end = g_rowptr[node + 1];
    const float4* Xv = (const float4*)X;
    float4 acc = Xv[(size_t)node * Q + q];
#pragma unroll 4
    for (int j = beg; j < end; j++) {
        int s = g_srcs[j];
        float4 v = Xv[(size_t)s * Q + q];
        acc.x += v.x; acc.y += v.y; acc.z += v.z; acc.w += v.w;
    }
    float d = g_dinv[node];
    acc.x *= d; acc.y *= d; acc.z *= d; acc.w *= d;
    if (BIAS) {
        float4 bv = ((const float4*)bias)[q];
        acc.x += bv.x; acc.y += bv.y; acc.z += bv.z; acc.w += bv.w;
    }
    if (RELU) {
        acc.x = fmaxf(acc.x, 0.f); acc.y = fmaxf(acc.y, 0.f);
        acc.z = fmaxf(acc.z, 0.f); acc.w = fmaxf(acc.w, 0.f);
    }
    ((float4*)Y)[(size_t)node * Q + q] = acc;
}

// ---------------- register-tiled matmul (for dec1: 64->32, dinv-scaled) ----------------
template <int CIN, int COUT, bool SCALE, bool BIAS, bool RELU>
__global__ void __launch_bounds__(256, 2)
k_mm(const float* __restrict__ X, const float* __restrict__ W,
     const float* __restrict__ bias, float* __restrict__ Y) {
    constexpr int ROWS = 256;
    constexpr int CPT = COUT / 8;
    constexpr int CP2 = CPT / 2;
    constexpr int XPITCH = CIN + 1;
    extern __shared__ float smem[];
    float* sX = smem;
    float* sW = smem + ROWS * XPITCH;

    int t = threadIdx.x;
    int row0 = blockIdx.x * ROWS;

    for (int i = t; i < CIN * COUT / 4; i += 256)
        ((float4*)sW)[i] = ((const float4*)W)[i];
    for (int i = t; i < ROWS * CIN; i += 256) {
        int r = i / CIN, k = i % CIN;
        int row = row0 + r;
        sX[r * XPITCH + k] = (row < N) ? X[(size_t)row * CIN + k] : 0.0f;
    }
    __syncthreads();

    int tc = t % 8, tr = t / 8;
    int c0 = tc * CPT, r0 = tr * 8;

    ull acc2[8][CP2];
    const ull zz = pack2(0.f, 0.f);
#pragma unroll
    for (int i = 0; i < 8; i++)
#pragma unroll
        for (int j = 0; j < CP2; j++) acc2[i][j] = zz;

#pragma unroll 8
    for (int k = 0; k < CIN; k++) {
        ull a2[8];
#pragma unroll
        for (int i = 0; i < 8; i++) {
            float av = sX[(r0 + i) * XPITCH + k];
            a2[i] = pack2(av, av);
        }
        ull b2[CP2];
#pragma unroll
        for (int v = 0; v < CPT / 4; v++) {
            ulonglong2 bb = *(const ulonglong2*)(sW + k * COUT + c0 + v * 4);
            b2[v * 2 + 0] = bb.x;
            b2[v * 2 + 1] = bb.y;
        }
#pragma unroll
        for (int i = 0; i < 8; i++)
#pragma unroll
            for (int j = 0; j < CP2; j++)
                fma2(acc2[i][j], a2[i], b2[j]);
    }

    float bv[CPT];
    if (BIAS) {
#pragma unroll
        for (int v = 0; v < CPT / 4; v++)
            *(float4*)(bv + v * 4) = *(const float4*)(bias + c0 + v * 4);
    }
#pragma unroll
    for (int i = 0; i < 8; i++) {
        int row = row0 + r0 + i;
        if (row >= N) continue;
        float s = SCALE ? g_dinv[row] : 1.0f;
        float o[CPT];
#pragma unroll
        for (int j = 0; j < CP2; j++) unpack2(o[2 * j], o[2 * j + 1], acc2[i][j]);
#pragma unroll
        for (int j = 0; j < CPT; j++) {
            float v = o[j] * s;
            if (BIAS) v += bv[j];
            if (RELU) v = fmaxf(v, 0.f);
            o[j] = v;
        }
#pragma unroll
        for (int v = 0; v < CPT / 4; v++)
            *(float4*)(Y + (size_t)row * COUT + c0 + v * 4) =
                make_float4(o[v*4+0], o[v*4+1], o[v*4+2], o[v*4+3]);
    }
}

// ---------------- latent projection: z = mean @ W_proj + b ----------------
__global__ void k_z(const float* __restrict__ Wp, const float* __restrict__ bp,
                    float* __restrict__ out_z) {
    int t = threadIdx.x;  // 1024 = G*L
    int g = t / L, l = t % L;
    float inv = 1.0f / fmaxf(g_cnt[g], 1.0f);
    float acc = bp[l];
#pragma unroll
    for (int c = 0; c < H; c++) acc = fmaf(g_pool[g * H + c] * inv, Wp[c * L + l], acc);
    g_z[t] = acc;
    out_z[t] = acc;
}

// ------- decoder broadcast: P_d = dinv * relu(z[batch] @ W_dec_proj + b) -------
__global__ void k_dec_bcast(const int* __restrict__ batch, const float* __restrict__ W,
                            const float* __restrict__ b, float* __restrict__ Y) {
    int idx = blockIdx.x * blockDim.x + threadIdx.x;  // N * 16
    if (idx >= N * 16) return;
    int i = idx >> 4, v = idx & 15;
    int gid = batch[i];
    float4 acc = ((const float4*)b)[v];
#pragma unroll
    for (int l = 0; l < L; l++) {
        float zl = g_z[gid * L + l];
        float4 w = ((const float4*)W)[l * 16 + v];
        acc.x = fmaf(zl, w.x, acc.x); acc.y = fmaf(zl, w.y, acc.y);
        acc.z = fmaf(zl, w.z, acc.z); acc.w = fmaf(zl, w.w, acc.w);
    }
    float d = g_dinv[i];
    acc.x = fmaxf(acc.x, 0.f) * d; acc.y = fmaxf(acc.y, 0.f) * d;
    acc.z = fmaxf(acc.z, 0.f) * d; acc.w = fmaxf(acc.w, 0.f) * d;
    ((float4*)Y)[idx] = acc;
}

// ---------------- launcher ----------------
extern "C" void kernel_launch(void* const* d_in, const int* in_sizes, int n_in,
                              void* d_out, int out_size) {
    const float* x       = (const float*)d_in[0];
    const int*   ei      = (const int*)d_in[1];
    const int*   src     = ei;
    const int*   dst     = ei + E;
    const int*   batch   = (const int*)d_in[2];
    const float* W_enc0  = (const float*)d_in[3];
    const float* b_enc0  = (const float*)d_in[4];
    const float* W_enc1  = (const float*)d_in[5];
    const float* b_enc1  = (const float*)d_in[6];
    const float* W_enc2  = (const float*)d_in[7];
    const float* b_enc2  = (const float*)d_in[8];
    const float* W_proj  = (const float*)d_in[9];
    const float* b_proj  = (const float*)d_in[10];
    const float* W_dproj = (const float*)d_in[11];
    const float* b_dproj = (const float*)d_in[12];
    const float* W_dec0  = (const float*)d_in[13];
    const float* b_dec0  = (const float*)d_in[14];
    const float* W_dec1  = (const float*)d_in[15];
    const float* b_dec1  = (const float*)d_in[16];

    float* out_recon = (float*)d_out;           // [N, IN]
    float* out_z     = (float*)d_out + N * IN;  // [G, L]

    float* buf0;  cudaGetSymbolAddress((void**)&buf0, g_buf0);
    float* buf1;  cudaGetSymbolAddress((void**)&buf1, g_buf1);
    int*   degp;  cudaGetSymbolAddress((void**)&degp, g_deg);
    float* poolp; cudaGetSymbolAddress((void**)&poolp, g_pool);
    float* cntp;  cudaGetSymbolAddress((void**)&cntp, g_cnt);

    const int T = 256;

    constexpr int SM_64_32 = (256 * 65 + 64 * 32) * 4;   // 73.0 KB (dec1 mm)
    static bool attr_done = false;
    if (!attr_done) {
        cudaFuncSetAttribute((const void*)k_mm<H, IN, true, false, false>,
                             cudaFuncAttributeMaxDynamicSharedMemorySize, SM_64_32);
        attr_done = true;
    }

    // ---- CSR build + dinv
    cudaMemsetAsync(degp, 0, N * sizeof(int));
    cudaMemsetAsync(poolp, 0, G * H * sizeof(float));
    cudaMemsetAsync(cntp, 0, G * sizeof(float));
    k_hist<<<CDIV(E, T), T>>>(dst);
    k_scan1<<<NB_SCAN, SCAN_CHUNK>>>();
    k_scan23<<<CDIV(N, T), T>>>();
    k_fill<<<CDIV(E, T), T>>>(src, dst);

    // ---- enc0: P0 = dinv*x; fused gather(C=32)+W_enc0 -> P1 (dinv-scaled)
    k_prescale32<<<CDIV(N * 8, T), T>>>(x, buf0);
    k_gmm<IN, H, 0><<<CDIV(N, 256), 256>>>(buf0, W_enc0, b_enc0, buf1, nullptr);

    // ---- enc1: fused gather(C=64)+W_enc1 -> P2
    k_gmm<H, H, 0><<<CDIV(N, 128), 256>>>(buf1, W_enc1, b_enc1, buf0, nullptr);

    // ---- enc2: fused gather+W_enc2, pool epilogue (no activation write)
    k_gmm<H, H, 1><<<CDIV(N, 128), 256>>>(buf0, W_enc2, b_enc2, nullptr, batch);

    // ---- latent projection
    k_z<<<1, G * L>>>(W_proj, b_proj, out_z);

    // ---- decoder broadcast -> P_d (dinv-scaled)
    k_dec_bcast<<<CDIV(N * 16, T), T>>>(batch, W_dproj, b_dproj, buf0);

    // ---- dec0: fused gather+W_dec0 -> h_d1 (unscaled, MODE 2)
    k_gmm<H, H, 2><<<CDIV(N, 128), 256>>>(buf0, W_dec0, b_dec0, buf1, nullptr);

    // ---- dec1: mm-first (dinv-scaled 64->32), then gather C=32 (+bias) -> out
    k_mm<H, IN, true, false, false><<<CDIV(N, 256), 256, SM_64_32>>>(buf1, W_dec1, nullptr, buf0);
    k_gather<IN, true, false><<<CDIV(N, 32), 256>>>(buf0, b_dec1, out_recon);
}

// round 8
// speedup vs baseline: 1.6615x; 1.6615x over previous
#include <cuda_runtime.h>
#include <cstdint>

// Problem constants (fixed by the reference)
constexpr int N  = 100000;
constexpr int E  = 1600000;
constexpr int IN = 32;
constexpr int H  = 64;
constexpr int L  = 16;
constexpr int G  = 64;

constexpr int SCAN_CHUNK = 512;
constexpr int NB_SCAN = (N + SCAN_CHUNK - 1) / SCAN_CHUNK;  // 196

#define CDIV(a, b) (((a) + (b) - 1) / (b))

// ---------------- tf32 mma helpers ----------------
__device__ __forceinline__ uint32_t f2tf32(float x) {
    uint32_t r;
    asm("cvt.rna.tf32.f32 %0, %1;" : "=r"(r) : "f"(x));
    return r;
}
__device__ __forceinline__ void mma_tf32(float c[4], uint32_t a0, uint32_t a1,
                                         uint32_t a2, uint32_t a3,
                                         uint32_t b0, uint32_t b1) {
    asm("mma.sync.aligned.m16n8k8.row.col.f32.tf32.tf32.f32 "
        "{%0,%1,%2,%3}, {%4,%5,%6,%7}, {%8,%9}, {%0,%1,%2,%3};"
        : "+f"(c[0]), "+f"(c[1]), "+f"(c[2]), "+f"(c[3])
        : "r"(a0), "r"(a1), "r"(a2), "r"(a3), "r"(b0), "r"(b1));
}

// ---------------- device scratch (no allocations allowed) ----------------
__device__ float g_buf0[N * H];
__device__ float g_buf1[N * H];
__device__ float g_dinv[N];
__device__ int   g_deg[N];
__device__ int   g_rowptr[N + 1];
__device__ int   g_cursor[N];
__device__ int   g_srcs[E];
__device__ int   g_bsum[256];
__device__ float g_pool[G * H];
__device__ float g_cnt[G];
__device__ float g_z[G * L];

// ---------------- degree histogram ----------------
__global__ void k_hist(const int* __restrict__ dst) {
    int e = blockIdx.x * blockDim.x + threadIdx.x;
    if (e < E) atomicAdd(&g_deg[dst[e]], 1);
}

// ---------------- scan pass 1 (also computes dinv) ----------------
__global__ void k_scan1() {
    __shared__ int s[SCAN_CHUNK];
    int t = threadIdx.x;
    int i = blockIdx.x * SCAN_CHUNK + t;
    int v = (i < N) ? g_deg[i] : 0;
    if (i < N) g_dinv[i] = rsqrtf((float)v + 1.0f);
    s[t] = v;
    __syncthreads();
#pragma unroll
    for (int off = 1; off < SCAN_CHUNK; off <<= 1) {
        int x = (t >= off) ? s[t - off] : 0;
        __syncthreads();
        s[t] += x;
        __syncthreads();
    }
    if (i < N) g_rowptr[i] = s[t] - v;
    if (t == SCAN_CHUNK - 1) g_bsum[blockIdx.x] = s[t];
}

// ---------------- fused scan2+scan3 ----------------
__global__ void k_scan23() {
    __shared__ int s[256];
    __shared__ int excl[256];
    int t = threadIdx.x;
    int v = (t < NB_SCAN) ? g_bsum[t] : 0;
    s[t] = v;
    __syncthreads();
#pragma unroll
    for (int off = 1; off < 256; off <<= 1) {
        int x = (t >= off) ? s[t - off] : 0;
        __syncthreads();
        s[t] += x;
        __syncthreads();
    }
    excl[t] = s[t] - v;
    __syncthreads();
    int i = blockIdx.x * blockDim.x + t;
    if (i < N) {
        int r = g_rowptr[i] + excl[i / SCAN_CHUNK];
        g_rowptr[i] = r;
        g_cursor[i] = r;
    }
    if (i == 0) g_rowptr[N] = E;
}

__global__ void k_fill(const int* __restrict__ src, const int* __restrict__ dst) {
    int e = blockIdx.x * blockDim.x + threadIdx.x;
    if (e >= E) return;
    int pos = atomicAdd(&g_cursor[dst[e]], 1);
    g_srcs[pos] = src[e];
}

// ---------------- prescale: P0 = x * dinv[row]  (C=32) ----------------
__global__ void k_prescale32(const float* __restrict__ X, float* __restrict__ Y) {
    int idx = blockIdx.x * blockDim.x + threadIdx.x;
    if (idx >= N * 8) return;
    int i = idx >> 3;
    float d = g_dinv[i];
    float4 v = ((const float4*)X)[idx];
    float4 o = {v.x * d, v.y * d, v.z * d, v.w * d};
    ((float4*)Y)[idx] = o;
}

// ---------------- CSR gather:  Y[i] = dinv[i]*(sum_src X[src] + X[i]) ----------------
template <int C, bool BIAS, bool RELU>
__global__ void k_gather(const float* __restrict__ X, const float* __restrict__ bias,
                         float* __restrict__ Y) {
    constexpr int Q = C / 4;
    constexpr int NPB = 256 / Q;
    int t = threadIdx.x;
    int node = blockIdx.x * NPB + t / Q;
    int q = t % Q;
    if (node >= N) return;
    int beg = g_rowptr[node];
    int end = g_rowptr[node + 1];
    const float4* Xv = (const float4*)X;
    float4 acc = Xv[(size_t)node * Q + q];
#pragma unroll 4
    for (int j = beg; j < end; j++) {
        int s = g_srcs[j];
        float4 v = Xv[(size_t)s * Q + q];
        acc.x += v.x; acc.y += v.y; acc.z += v.z; acc.w += v.w;
    }
    float d = g_dinv[node];
    acc.x *= d; acc.y *= d; acc.z *= d; acc.w *= d;
    if (BIAS) {
        float4 bv = ((const float4*)bias)[q];
        acc.x += bv.x; acc.y += bv.y; acc.z += bv.z; acc.w += bv.w;
    }
    if (RELU) {
        acc.x = fmaxf(acc.x, 0.f); acc.y = fmaxf(acc.y, 0.f);
        acc.z = fmaxf(acc.z, 0.f); acc.w = fmaxf(acc.w, 0.f);
    }
    ((float4*)Y)[(size_t)node * Q + q] = acc;
}

// =====================================================================
// Tensor-core per-node matmul (tf32 mma.sync, fp32 accumulate).
// Block = 256 threads (8 warps), 128 rows; warp computes 16 rows x COUT.
// A staged in smem at pitch CIN+4 (bank = 4r+c -> conflict-free frags).
// B pre-swizzled into fragment order (lane-consecutive float2, LDS.64).
// =====================================================================
template <int CIN, int COUT, bool SCALE, bool BIAS, bool RELU>
__global__ void __launch_bounds__(256)
k_mmt(const float* __restrict__ X, const float* __restrict__ W,
      const float* __restrict__ bias, float* __restrict__ Y) {
    constexpr int ROWS = 128;
    constexpr int KC = CIN / 8;     // k-chunks
    constexpr int NT = COUT / 8;    // n-tiles
    constexpr int PITCHA = CIN + 4; // (CIN+4) mod 32 == 4 -> bank 4r+c unique
    extern __shared__ char smem_raw[];
    uint32_t* sA = (uint32_t*)smem_raw;                          // ROWS*PITCHA
    float2*   sB = (float2*)(smem_raw + ROWS * PITCHA * 4);      // KC*NT*32

    int t = threadIdx.x;
    int row0 = blockIdx.x * ROWS;

    // stage A (convert to tf32)
    for (int i = t; i < ROWS * CIN / 4; i += 256) {
        int r = i / (CIN / 4), c4 = (i % (CIN / 4)) * 4;
        int row = row0 + r;
        float4 v = (row < N) ? ((const float4*)X)[(size_t)row * (CIN / 4) + c4 / 4]
                             : make_float4(0.f, 0.f, 0.f, 0.f);
        uint32_t* p = sA + r * PITCHA + c4;
        p[0] = f2tf32(v.x); p[1] = f2tf32(v.y);
        p[2] = f2tf32(v.z); p[3] = f2tf32(v.w);
    }
    // stage B in fragment order
    for (int i = t; i < KC * NT * 32; i += 256) {
        int lane = i & 31, tile = i >> 5;
        int kc = tile / NT, nt = tile % NT;
        int kr = kc * 8 + (lane & 3);
        int c  = nt * 8 + (lane >> 2);
        float b0 = W[kr * COUT + c];
        float b1 = W[(kr + 4) * COUT + c];
        sB[i] = make_float2(__uint_as_float(f2tf32(b0)), __uint_as_float(f2tf32(b1)));
    }
    __syncthreads();

    int w = t >> 5, lane = t & 31;
    int r0 = w * 16;
    int lr = lane >> 2, lc = lane & 3;

    float acc[NT][4];
#pragma unroll
    for (int nt = 0; nt < NT; nt++)
#pragma unroll
        for (int j = 0; j < 4; j++) acc[nt][j] = 0.f;

#pragma unroll
    for (int kc = 0; kc < KC; kc++) {
        const uint32_t* base = sA + kc * 8 + lc;
        uint32_t a0 = base[(r0 + lr) * PITCHA];
        uint32_t a1 = base[(r0 + lr + 8) * PITCHA];
        uint32_t a2 = base[(r0 + lr) * PITCHA + 4];
        uint32_t a3 = base[(r0 + lr + 8) * PITCHA + 4];
#pragma unroll
        for (int nt = 0; nt < NT; nt++) {
            float2 b = sB[(kc * NT + nt) * 32 + lane];
            mma_tf32(acc[nt], a0, a1, a2, a3,
                     __float_as_uint(b.x), __float_as_uint(b.y));
        }
    }

    // epilogue
    int ra = row0 + r0 + lr;
    int rb = ra + 8;
    float sa = 1.f, sb = 1.f;
    if (SCALE) {
        if (ra < N) sa = g_dinv[ra];
        if (rb < N) sb = g_dinv[rb];
    }
#pragma unroll
    for (int nt = 0; nt < NT; nt++) {
        int c = nt * 8 + 2 * lc;
        float b0v = 0.f, b1v = 0.f;
        if (BIAS) { b0v = bias[c]; b1v = bias[c + 1]; }
        if (ra < N) {
            float o0 = acc[nt][0] * sa + b0v;
            float o1 = acc[nt][1] * sa + b1v;
            if (RELU) { o0 = fmaxf(o0, 0.f); o1 = fmaxf(o1, 0.f); }
            *(float2*)(Y + (size_t)ra * COUT + c) = make_float2(o0, o1);
        }
        if (rb < N) {
            float o2 = acc[nt][2] * sb + b0v;
            float o3 = acc[nt][3] * sb + b1v;
            if (RELU) { o2 = fmaxf(o2, 0.f); o3 = fmaxf(o3, 0.f); }
            *(float2*)(Y + (size_t)rb * COUT + c) = make_float2(o2, o3);
        }
    }
}

// ---------------- global mean pool (sorted batch, run-length) + counts ----------------
__global__ void k_pool_acc(const int* __restrict__ batch, const float* __restrict__ Hf) {
    int t = threadIdx.x;
    int c = t % 64;
    int base = blockIdx.x * 128;
    float acc = 0.f;
    float cntacc = 0.f;
    int cur = -1;
    for (int j = t / 64; j < 128; j += 4) {
        int i = base + j;
        if (i >= N) break;
        int g = batch[i];
        if (g != cur) {
            if (cur >= 0) {
                atomicAdd(&g_pool[cur * 64 + c], acc);
                if (c == 0) atomicAdd(&g_cnt[cur], cntacc);
            }
            cur = g; acc = 0.f; cntacc = 0.f;
        }
        acc += Hf[(size_t)i * 64 + c];
        cntacc += 1.f;
    }
    if (cur >= 0) {
        atomicAdd(&g_pool[cur * 64 + c], acc);
        if (c == 0) atomicAdd(&g_cnt[cur], cntacc);
    }
}

// ---------------- latent projection: z = mean @ W_proj + b ----------------
__global__ void k_z(const float* __restrict__ Wp, const float* __restrict__ bp,
                    float* __restrict__ out_z) {
    int t = threadIdx.x;  // 1024 = G*L
    int g = t / L, l = t % L;
    float inv = 1.0f / fmaxf(g_cnt[g], 1.0f);
    float acc = bp[l];
#pragma unroll
    for (int c = 0; c < H; c++) acc = fmaf(g_pool[g * H + c] * inv, Wp[c * L + l], acc);
    g_z[t] = acc;
    out_z[t] = acc;
}

// ------- decoder broadcast: h_d = relu(z[batch] @ W_dec_proj + b) -------
__global__ void k_dec_bcast(const int* __restrict__ batch, const float* __restrict__ W,
                            const float* __restrict__ b, float* __restrict__ Y) {
    int idx = blockIdx.x * blockDim.x + threadIdx.x;  // N * 16
    if (idx >= N * 16) return;
    int i = idx >> 4, v = idx & 15;
    int gid = batch[i];
    float4 acc = ((const float4*)b)[v];
#pragma unroll
    for (int l = 0; l < L; l++) {
        float zl = g_z[gid * L + l];
        float4 w = ((const float4*)W)[l * 16 + v];
        acc.x = fmaf(zl, w.x, acc.x); acc.y = fmaf(zl, w.y, acc.y);
        acc.z = fmaf(zl, w.z, acc.z); acc.w = fmaf(zl, w.w, acc.w);
    }
    acc.x = fmaxf(acc.x, 0.f); acc.y = fmaxf(acc.y, 0.f);
    acc.z = fmaxf(acc.z, 0.f); acc.w = fmaxf(acc.w, 0.f);
    ((float4*)Y)[idx] = acc;
}

// ---------------- launcher ----------------
extern "C" void kernel_launch(void* const* d_in, const int* in_sizes, int n_in,
                              void* d_out, int out_size) {
    const float* x       = (const float*)d_in[0];
    const int*   ei      = (const int*)d_in[1];
    const int*   src     = ei;
    const int*   dst     = ei + E;
    const int*   batch   = (const int*)d_in[2];
    const float* W_enc0  = (const float*)d_in[3];
    const float* b_enc0  = (const float*)d_in[4];
    const float* W_enc1  = (const float*)d_in[5];
    const float* b_enc1  = (const float*)d_in[6];
    const float* W_enc2  = (const float*)d_in[7];
    const float* b_enc2  = (const float*)d_in[8];
    const float* W_proj  = (const float*)d_in[9];
    const float* b_proj  = (const float*)d_in[10];
    const float* W_dproj = (const float*)d_in[11];
    const float* b_dproj = (const float*)d_in[12];
    const float* W_dec0  = (const float*)d_in[13];
    const float* b_dec0  = (const float*)d_in[14];
    const float* W_dec1  = (const float*)d_in[15];
    const float* b_dec1  = (const float*)d_in[16];

    float* out_recon = (float*)d_out;           // [N, IN]
    float* out_z     = (float*)d_out + N * IN;  // [G, L]

    float* buf0;  cudaGetSymbolAddress((void**)&buf0, g_buf0);
    float* buf1;  cudaGetSymbolAddress((void**)&buf1, g_buf1);
    int*   degp;  cudaGetSymbolAddress((void**)&degp, g_deg);
    float* poolp; cudaGetSymbolAddress((void**)&poolp, g_pool);
    float* cntp;  cudaGetSymbolAddress((void**)&cntp, g_cnt);

    const int T = 256;

    // dynamic smem: A tile (128 x (CIN+4) u32) + B fragments (KC*NT*32 float2)
    constexpr int SMT_32_64 = 128 * 36 * 4 + (4 * 8 * 32) * 8;   // 26624
    constexpr int SMT_64_64 = 128 * 68 * 4 + (8 * 8 * 32) * 8;   // 51200
    constexpr int SMT_64_32 = 128 * 68 * 4 + (8 * 4 * 32) * 8;   // 43008
    static bool attr_done = false;
    if (!attr_done) {
        cudaFuncSetAttribute((const void*)k_mmt<IN, H, false, true, true>,
                             cudaFuncAttributeMaxDynamicSharedMemorySize, SMT_32_64);
        cudaFuncSetAttribute((const void*)k_mmt<H, H, true, false, false>,
                             cudaFuncAttributeMaxDynamicSharedMemorySize, SMT_64_64);
        cudaFuncSetAttribute((const void*)k_mmt<H, IN, true, false, false>,
                             cudaFuncAttributeMaxDynamicSharedMemorySize, SMT_64_32);
        attr_done = true;
    }

    // ---- CSR build + dinv
    cudaMemsetAsync(degp, 0, N * sizeof(int));
    cudaMemsetAsync(poolp, 0, G * H * sizeof(float));
    cudaMemsetAsync(cntp, 0, G * sizeof(float));
    k_hist<<<CDIV(E, T), T>>>(dst);
    k_scan1<<<NB_SCAN, SCAN_CHUNK>>>();
    k_scan23<<<CDIV(N, T), T>>>();
    k_fill<<<CDIV(E, T), T>>>(src, dst);

    const int MMB = CDIV(N, 128);

    // ---- enc0: aggregate x at C=32, then 32->64 matmul (+bias+relu)
    k_prescale32<<<CDIV(N * 8, T), T>>>(x, buf0);
    k_gather<IN, false, false><<<CDIV(N, 32), 256>>>(buf0, nullptr, buf1);
    k_mmt<IN, H, false, true, true><<<MMB, 256, SMT_32_64>>>(buf1, W_enc0, b_enc0, buf0);

    // ---- enc1
    k_mmt<H, H, true, false, false><<<MMB, 256, SMT_64_64>>>(buf0, W_enc1, nullptr, buf1);
    k_gather<H, true, true><<<CDIV(N, 16), 256>>>(buf1, b_enc1, buf0);

    // ---- enc2
    k_mmt<H, H, true, false, false><<<MMB, 256, SMT_64_64>>>(buf0, W_enc2, nullptr, buf1);
    k_gather<H, true, true><<<CDIV(N, 16), 256>>>(buf1, b_enc2, buf0);

    // ---- global mean pool + latent projection
    k_pool_acc<<<CDIV(N, 128), 256>>>(batch, buf0);
    k_z<<<1, G * L>>>(W_proj, b_proj, out_z);

    // ---- decoder broadcast
    k_dec_bcast<<<CDIV(N * 16, T), T>>>(batch, W_dproj, b_dproj, buf0);

    // ---- dec0
    k_mmt<H, H, true, false, false><<<MMB, 256, SMT_64_64>>>(buf0, W_dec0, nullptr, buf1);
    k_gather<H, true, true><<<CDIV(N, 16), 256>>>(buf1, b_dec0, buf0);

    // ---- dec1: 64->32 matmul (dinv-scaled), gather at C=32 into d_out
    k_mmt<H, IN, true, false, false><<<MMB, 256, SMT_64_32>>>(buf0, W_dec1, nullptr, buf1);
    k_gather<IN, true, false><<<CDIV(N, 32), 256>>>(buf1, b_dec1, out_recon);
}